// round 1
// baseline (speedup 1.0000x reference)
#include <cuda_runtime.h>
#include <math.h>

#define BB 4
#define TT 1024
#define TEXPR 1022
#define DIN 64
#define DD 256
#define HH 8
#define DHD 32
#define LL 4
#define FF 512
#define M_TOK (BB*TEXPR)   // 4088
#define M_X (BB*TT)        // 4096

// ---------------- scratch (static device globals; no allocation) ----------------
__device__ float g_h  [M_TOK*DD];
__device__ float g_tok[M_TOK*DD];
__device__ float g_x  [M_X*DD];
__device__ float g_q  [M_X*DD];
__device__ float g_k  [M_X*DD];
__device__ float g_v  [M_X*DD];
__device__ float g_ao [M_X*DD];
__device__ float g_tmp[M_X*DD];
__device__ float g_ffn[M_X*FF];

// ---------------- helpers ----------------
__device__ __forceinline__ float gelu_tanh(float x) {
    // JAX approximate gelu (tanh form)
    float x3 = x * x * x;
    return 0.5f * x * (1.0f + tanhf(0.7978845608028654f * (x + 0.044715f * x3)));
}

// ---------------- generic tiled GEMM: C[M,N] = act(A[M,K] @ W[K,N] + bias[N]) ----------------
// 64x64 block tile, BK=16, 256 threads, 4x4 per-thread microtile.
template<int ACT>  // 0 = none, 1 = gelu
__global__ void __launch_bounds__(256) gemm_kernel(
    const float* __restrict__ A, const float* __restrict__ W,
    const float* __restrict__ bias, float* __restrict__ C,
    int M, int N, int K)
{
    __shared__ float As[16][64];   // As[k][m]
    __shared__ float Ws[16][64];   // Ws[k][n]

    const int tid = threadIdx.x;
    const int tx = tid & 15;       // 0..15 (n)
    const int ty = tid >> 4;       // 0..15 (m)
    const int bm = blockIdx.y * 64;
    const int bn = blockIdx.x * 64;

    const int arow = tid >> 2;          // 0..63
    const int ak   = (tid & 3) * 4;     // 0,4,8,12
    const int wrow = tid >> 4;          // 0..15
    const int wcol = (tid & 15) * 4;    // 0..60

    float acc[4][4];
    #pragma unroll
    for (int i = 0; i < 4; i++)
        #pragma unroll
        for (int j = 0; j < 4; j++) acc[i][j] = 0.0f;

    for (int kt = 0; kt < K; kt += 16) {
        float4 av = make_float4(0.f, 0.f, 0.f, 0.f);
        if (bm + arow < M)
            av = *(const float4*)(A + (size_t)(bm + arow) * K + kt + ak);
        As[ak + 0][arow] = av.x;
        As[ak + 1][arow] = av.y;
        As[ak + 2][arow] = av.z;
        As[ak + 3][arow] = av.w;

        float4 wv = *(const float4*)(W + (size_t)(kt + wrow) * N + bn + wcol);
        *(float4*)&Ws[wrow][wcol] = wv;
        __syncthreads();

        #pragma unroll
        for (int kk = 0; kk < 16; kk++) {
            float4 a4 = *(const float4*)&As[kk][ty * 4];
            float4 b4 = *(const float4*)&Ws[kk][tx * 4];
            float a[4] = {a4.x, a4.y, a4.z, a4.w};
            float b[4] = {b4.x, b4.y, b4.z, b4.w};
            #pragma unroll
            for (int i = 0; i < 4; i++)
                #pragma unroll
                for (int j = 0; j < 4; j++)
                    acc[i][j] += a[i] * b[j];
        }
        __syncthreads();
    }

    float4 bv = *(const float4*)(bias + bn + tx * 4);
    float bb[4] = {bv.x, bv.y, bv.z, bv.w};
    #pragma unroll
    for (int i = 0; i < 4; i++) {
        int row = bm + ty * 4 + i;
        if (row < M) {
            float o0 = acc[i][0] + bb[0];
            float o1 = acc[i][1] + bb[1];
            float o2 = acc[i][2] + bb[2];
            float o3 = acc[i][3] + bb[3];
            if (ACT == 1) {
                o0 = gelu_tanh(o0); o1 = gelu_tanh(o1);
                o2 = gelu_tanh(o2); o3 = gelu_tanh(o3);
            }
            *(float4*)(C + (size_t)row * N + bn + tx * 4) = make_float4(o0, o1, o2, o3);
        }
    }
}

// ---------------- assemble x = concat([cls, emb[drug], tok]) ----------------
__global__ void assemble_kernel(
    const float* __restrict__ tok, const float* __restrict__ emb_table,
    const float* __restrict__ cls, const int* __restrict__ drug,
    float* __restrict__ X)
{
    int idx = blockIdx.x * blockDim.x + threadIdx.x;
    if (idx >= M_X * DD) return;
    int r = idx >> 8;       // row   (idx / 256)
    int d = idx & 255;      // col
    int b = r >> 10;        // r / 1024
    int t = r & 1023;       // r % 1024
    float val;
    if (t == 0)      val = cls[d];
    else if (t == 1) val = emb_table[(size_t)drug[b] * DD + d];
    else             val = tok[(size_t)(b * TEXPR + (t - 2)) * DD + d];
    X[idx] = val;
}

// ---------------- flash-style attention ----------------
// grid: (4 q-tiles of 256 rows, B*H).  One thread = one q row.  Online softmax.
__global__ void __launch_bounds__(256) attn_kernel(
    const float* __restrict__ Q, const float* __restrict__ K,
    const float* __restrict__ V, float* __restrict__ O)
{
    __shared__ float4 Ks[32 * 8];
    __shared__ float4 Vs[32 * 8];

    const int tid = threadIdx.x;
    const int bh = blockIdx.y;
    const int b = bh >> 3;
    const int h = bh & 7;
    const int qrow = blockIdx.x * 256 + tid;

    const float* Qp = Q + (size_t)(b * TT + qrow) * DD + h * DHD;
    float q[32];
    #pragma unroll
    for (int i = 0; i < 8; i++) {
        float4 v = *(const float4*)(Qp + i * 4);
        q[i * 4 + 0] = v.x; q[i * 4 + 1] = v.y;
        q[i * 4 + 2] = v.z; q[i * 4 + 3] = v.w;
    }

    float o[32];
    #pragma unroll
    for (int d = 0; d < 32; d++) o[d] = 0.0f;
    float m = -INFINITY;
    float l = 0.0f;

    const int krow = tid >> 3;   // 0..31
    const int kc   = tid & 7;    // 0..7
    const float scale = 0.0625f; // 1/sqrt(256)

    for (int kt = 0; kt < TT; kt += 32) {
        const float* Kp = K + (size_t)(b * TT + kt + krow) * DD + h * DHD + kc * 4;
        const float* Vp = V + (size_t)(b * TT + kt + krow) * DD + h * DHD + kc * 4;
        Ks[krow * 8 + kc] = *(const float4*)Kp;
        Vs[krow * 8 + kc] = *(const float4*)Vp;
        __syncthreads();

        float s[32];
        float tmax = -INFINITY;
        #pragma unroll
        for (int j = 0; j < 32; j++) {
            float acc = 0.0f;
            #pragma unroll
            for (int d = 0; d < 8; d++) {
                float4 kv = Ks[j * 8 + d];
                acc += q[d * 4 + 0] * kv.x + q[d * 4 + 1] * kv.y
                     + q[d * 4 + 2] * kv.z + q[d * 4 + 3] * kv.w;
            }
            s[j] = acc * scale;
            tmax = fmaxf(tmax, s[j]);
        }
        float newm = fmaxf(m, tmax);
        float corr = __expf(m - newm);
        l *= corr;
        #pragma unroll
        for (int d = 0; d < 32; d++) o[d] *= corr;

        #pragma unroll
        for (int j = 0; j < 32; j++) {
            float p = __expf(s[j] - newm);
            l += p;
            #pragma unroll
            for (int d = 0; d < 8; d++) {
                float4 vv = Vs[j * 8 + d];
                o[d * 4 + 0] += p * vv.x; o[d * 4 + 1] += p * vv.y;
                o[d * 4 + 2] += p * vv.z; o[d * 4 + 3] += p * vv.w;
            }
        }
        m = newm;
        __syncthreads();
    }

    float inv = 1.0f / l;
    float* Op = O + (size_t)(b * TT + qrow) * DD + h * DHD;
    #pragma unroll
    for (int i = 0; i < 8; i++) {
        *(float4*)(Op + i * 4) = make_float4(o[i * 4 + 0] * inv, o[i * 4 + 1] * inv,
                                             o[i * 4 + 2] * inv, o[i * 4 + 3] * inv);
    }
}

// ---------------- fused residual-add + LayerNorm (in-place on X) ----------------
__global__ void __launch_bounds__(256) add_ln_kernel(
    float* __restrict__ X, const float* __restrict__ Tm,
    const float* __restrict__ s, const float* __restrict__ bvec)
{
    const int row = blockIdx.x;
    const int tid = threadIdx.x;
    __shared__ float red[8];
    __shared__ float meanS, rstdS;

    float v = X[(size_t)row * DD + tid] + Tm[(size_t)row * DD + tid];

    float sum = v;
    #pragma unroll
    for (int off = 16; off > 0; off >>= 1) sum += __shfl_xor_sync(0xffffffffu, sum, off);
    if ((tid & 31) == 0) red[tid >> 5] = sum;
    __syncthreads();
    if (tid < 32) {
        float t = (tid < 8) ? red[tid] : 0.0f;
        t += __shfl_xor_sync(0xffffffffu, t, 4);
        t += __shfl_xor_sync(0xffffffffu, t, 2);
        t += __shfl_xor_sync(0xffffffffu, t, 1);
        if (tid == 0) meanS = t * (1.0f / 256.0f);
    }
    __syncthreads();
    float mean = meanS;
    float dc = v - mean;

    float sq = dc * dc;
    #pragma unroll
    for (int off = 16; off > 0; off >>= 1) sq += __shfl_xor_sync(0xffffffffu, sq, off);
    __syncthreads();   // protect red[] reuse
    if ((tid & 31) == 0) red[tid >> 5] = sq;
    __syncthreads();
    if (tid < 32) {
        float t = (tid < 8) ? red[tid] : 0.0f;
        t += __shfl_xor_sync(0xffffffffu, t, 4);
        t += __shfl_xor_sync(0xffffffffu, t, 2);
        t += __shfl_xor_sync(0xffffffffu, t, 1);
        if (tid == 0) rstdS = rsqrtf(t * (1.0f / 256.0f) + 1e-6f);
    }
    __syncthreads();

    X[(size_t)row * DD + tid] = dc * rstdS * s[tid] + bvec[tid];
}

// ---------------- final output: (x[:,0,:], zeros) ----------------
__global__ void out_kernel(const float* __restrict__ X, float* __restrict__ out, int out_size)
{
    int i = blockIdx.x * blockDim.x + threadIdx.x;
    if (i >= out_size) return;
    if (i < BB * DD) {
        int b = i >> 8, d = i & 255;
        out[i] = X[(size_t)(b * TT) * DD + d];
    } else {
        out[i] = 0.0f;
    }
}

// ---------------- host launcher ----------------
extern "C" void kernel_launch(void* const* d_in, const int* in_sizes, int n_in,
                              void* d_out, int out_size)
{
    const float* x_expr    = (const float*)d_in[0];
    const int*   drug_idx  = (const int*)  d_in[1];
    // d_in[2] = attn_mask (constant all-True in this problem -> no-op)
    const float* tok_W1    = (const float*)d_in[3];
    const float* tok_b1    = (const float*)d_in[4];
    const float* tok_W2    = (const float*)d_in[5];
    const float* tok_b2    = (const float*)d_in[6];
    const float* emb_table = (const float*)d_in[7];
    const float* cls_token = (const float*)d_in[8];
    const float* Wq = (const float*)d_in[9];
    const float* bq = (const float*)d_in[10];
    const float* Wk = (const float*)d_in[11];
    const float* bk = (const float*)d_in[12];
    const float* Wv = (const float*)d_in[13];
    const float* bv = (const float*)d_in[14];
    const float* Wo = (const float*)d_in[15];
    const float* bo = (const float*)d_in[16];
    const float* ln1_s = (const float*)d_in[17];
    const float* ln1_b = (const float*)d_in[18];
    const float* Wf1 = (const float*)d_in[19];
    const float* bf1 = (const float*)d_in[20];
    const float* Wf2 = (const float*)d_in[21];
    const float* bf2 = (const float*)d_in[22];
    const float* ln2_s = (const float*)d_in[23];
    const float* ln2_b = (const float*)d_in[24];
    float* out = (float*)d_out;

    float *px, *ph, *ptok, *pq, *pk, *pv, *pao, *ptmp, *pffn;
    cudaGetSymbolAddress((void**)&px,   g_x);
    cudaGetSymbolAddress((void**)&ph,   g_h);
    cudaGetSymbolAddress((void**)&ptok, g_tok);
    cudaGetSymbolAddress((void**)&pq,   g_q);
    cudaGetSymbolAddress((void**)&pk,   g_k);
    cudaGetSymbolAddress((void**)&pv,   g_v);
    cudaGetSymbolAddress((void**)&pao,  g_ao);
    cudaGetSymbolAddress((void**)&ptmp, g_tmp);
    cudaGetSymbolAddress((void**)&pffn, g_ffn);

    // token MLP
    {
        dim3 grid1(DD / 64, (M_TOK + 63) / 64);
        gemm_kernel<1><<<grid1, 256>>>(x_expr, tok_W1, tok_b1, ph, M_TOK, DD, DIN);
        gemm_kernel<1><<<grid1, 256>>>(ph, tok_W2, tok_b2, ptok, M_TOK, DD, DD);
    }
    // assemble x
    assemble_kernel<<<(M_X * DD + 255) / 256, 256>>>(ptok, emb_table, cls_token, drug_idx, px);

    dim3 gD(DD / 64, M_X / 64);     // N=256 GEMMs on 4096 rows
    dim3 gF(FF / 64, M_X / 64);     // N=512 GEMM
    dim3 gA(TT / 256, BB * HH);     // attention

    for (int l = 0; l < LL; l++) {
        const float* wq = Wq + (size_t)l * DD * DD;
        const float* wk = Wk + (size_t)l * DD * DD;
        const float* wv = Wv + (size_t)l * DD * DD;
        const float* wo = Wo + (size_t)l * DD * DD;
        gemm_kernel<0><<<gD, 256>>>(px, wq, bq + l * DD, pq, M_X, DD, DD);
        gemm_kernel<0><<<gD, 256>>>(px, wk, bk + l * DD, pk, M_X, DD, DD);
        gemm_kernel<0><<<gD, 256>>>(px, wv, bv + l * DD, pv, M_X, DD, DD);
        attn_kernel<<<gA, 256>>>(pq, pk, pv, pao);
        gemm_kernel<0><<<gD, 256>>>(pao, wo, bo + l * DD, ptmp, M_X, DD, DD);
        add_ln_kernel<<<M_X, 256>>>(px, ptmp, ln1_s + l * DD, ln1_b + l * DD);
        gemm_kernel<1><<<gF, 256>>>(px, Wf1 + (size_t)l * DD * FF, bf1 + l * FF, pffn, M_X, FF, DD);
        gemm_kernel<0><<<gD, 256>>>(pffn, Wf2 + (size_t)l * FF * DD, bf2 + l * DD, ptmp, M_X, DD, FF);
        add_ln_kernel<<<M_X, 256>>>(px, ptmp, ln2_s + l * DD, ln2_b + l * DD);
    }

    out_kernel<<<(out_size + 255) / 256, 256>>>(px, out, out_size);
}

// round 2
// speedup vs baseline: 1.4790x; 1.4790x over previous
#include <cuda_runtime.h>
#include <math.h>

#define BB 4
#define TT 1024
#define TEXPR 1022
#define DIN 64
#define DD 256
#define HH 8
#define DHD 32
#define LL 4
#define FF 512
#define M_TOK (BB*TEXPR)   // 4088
#define M_X (BB*TT)        // 4096

// ---------------- scratch (static device globals; no allocation) ----------------
__device__ float g_h  [M_TOK*DD];
__device__ float g_tok[M_TOK*DD];
__device__ float g_x  [M_X*DD];
__device__ float g_q  [M_X*DD];
__device__ float g_k  [M_X*DD];
__device__ float g_v  [M_X*DD];
__device__ float g_ao [M_X*DD];
__device__ float g_tmp[M_X*DD];
__device__ float g_ffn[M_X*FF];

// ---------------- helpers ----------------
__device__ __forceinline__ float gelu_tanh(float x) {
    float x3 = x * x * x;
    return 0.5f * x * (1.0f + tanhf(0.7978845608028654f * (x + 0.044715f * x3)));
}

__device__ __forceinline__ unsigned f2tf(float x) {
    unsigned r;
    asm("cvt.rna.tf32.f32 %0, %1;" : "=r"(r) : "f"(x));
    return r;
}

__device__ __forceinline__ void mma_tf32(float c[4], const unsigned a[4], const unsigned b[2]) {
    asm volatile(
        "mma.sync.aligned.m16n8k8.row.col.f32.tf32.tf32.f32 "
        "{%0,%1,%2,%3}, {%4,%5,%6,%7}, {%8,%9}, {%0,%1,%2,%3};\n"
        : "+f"(c[0]), "+f"(c[1]), "+f"(c[2]), "+f"(c[3])
        : "r"(a[0]), "r"(a[1]), "r"(a[2]), "r"(a[3]), "r"(b[0]), "r"(b[1]));
}

// ---------------- tensor-core tf32 GEMM: C[M,N] = act(A[M,K] @ W[K,N] + bias[N]) ----------------
// 128x64 block tile, BK=32, 256 threads (8 warps in 4x2), warp tile 32x32.
template<int ACT>  // 0 = none, 1 = gelu
__global__ void __launch_bounds__(256) gemm_tc(
    const float* __restrict__ A, const float* __restrict__ W,
    const float* __restrict__ bias, float* __restrict__ C,
    int M, int N, int K)
{
    __shared__ unsigned As[128][36];  // [m][k], stride 36 -> conflict-free frag loads
    __shared__ unsigned Bs[32][72];   // [k][n], stride 72 -> conflict-free frag loads

    const int tid  = threadIdx.x;
    const int lane = tid & 31;
    const int warp = tid >> 5;
    const int wm   = warp >> 1;       // 0..3
    const int wn   = warp & 1;        // 0..1
    const int bm   = blockIdx.y * 128;
    const int bn   = blockIdx.x * 64;
    const int g    = lane >> 2;       // groupID (0..7)
    const int tg   = lane & 3;        // thread-in-group (0..3)

    float acc[2][4][4];
    #pragma unroll
    for (int i = 0; i < 2; i++)
        #pragma unroll
        for (int j = 0; j < 4; j++)
            #pragma unroll
            for (int r = 0; r < 4; r++) acc[i][j][r] = 0.0f;

    // global-load index precompute
    int arow[4], acol[4], brow[2], bcol[2];
    #pragma unroll
    for (int i = 0; i < 4; i++) { int idx = tid + i * 256; arow[i] = idx >> 3; acol[i] = (idx & 7) * 4; }
    #pragma unroll
    for (int i = 0; i < 2; i++) { int idx = tid + i * 256; brow[i] = idx >> 4; bcol[i] = (idx & 15) * 4; }

    float4 ra[4], rb[2];

    // load tile kt into staging registers
    auto ldtile = [&](int kt) {
        #pragma unroll
        for (int i = 0; i < 4; i++) {
            if (bm + arow[i] < M)
                ra[i] = *(const float4*)(A + (size_t)(bm + arow[i]) * K + kt + acol[i]);
            else
                ra[i] = make_float4(0.f, 0.f, 0.f, 0.f);
        }
        #pragma unroll
        for (int i = 0; i < 2; i++)
            rb[i] = *(const float4*)(W + (size_t)(kt + brow[i]) * N + bn + bcol[i]);
    };

    ldtile(0);

    for (int kt = 0; kt < K; kt += 32) {
        __syncthreads();
        #pragma unroll
        for (int i = 0; i < 4; i++)
            *(uint4*)&As[arow[i]][acol[i]] =
                make_uint4(f2tf(ra[i].x), f2tf(ra[i].y), f2tf(ra[i].z), f2tf(ra[i].w));
        #pragma unroll
        for (int i = 0; i < 2; i++)
            *(uint4*)&Bs[brow[i]][bcol[i]] =
                make_uint4(f2tf(rb[i].x), f2tf(rb[i].y), f2tf(rb[i].z), f2tf(rb[i].w));
        __syncthreads();

        if (kt + 32 < K) ldtile(kt + 32);  // prefetch next tile (hidden under mma)

        #pragma unroll
        for (int ks = 0; ks < 4; ks++) {
            const int k = ks * 8;
            unsigned a[2][4], b[4][2];
            #pragma unroll
            for (int i = 0; i < 2; i++) {
                const int r = wm * 32 + i * 16;
                a[i][0] = As[r + g][k + tg];
                a[i][1] = As[r + g + 8][k + tg];
                a[i][2] = As[r + g][k + tg + 4];
                a[i][3] = As[r + g + 8][k + tg + 4];
            }
            #pragma unroll
            for (int j = 0; j < 4; j++) {
                const int c = wn * 32 + j * 8 + g;
                b[j][0] = Bs[k + tg][c];
                b[j][1] = Bs[k + tg + 4][c];
            }
            #pragma unroll
            for (int i = 0; i < 2; i++)
                #pragma unroll
                for (int j = 0; j < 4; j++)
                    mma_tf32(acc[i][j], a[i], b[j]);
        }
    }

    // epilogue: bias + optional gelu
    #pragma unroll
    for (int i = 0; i < 2; i++) {
        #pragma unroll
        for (int j = 0; j < 4; j++) {
            const int col = bn + wn * 32 + j * 8 + tg * 2;
            const float b0 = bias[col], b1 = bias[col + 1];
            const int row0 = bm + wm * 32 + i * 16 + g;
            const int row1 = row0 + 8;
            float v0 = acc[i][j][0] + b0, v1 = acc[i][j][1] + b1;
            float v2 = acc[i][j][2] + b0, v3 = acc[i][j][3] + b1;
            if (ACT == 1) { v0 = gelu_tanh(v0); v1 = gelu_tanh(v1); v2 = gelu_tanh(v2); v3 = gelu_tanh(v3); }
            if (row0 < M) *(float2*)(C + (size_t)row0 * N + col) = make_float2(v0, v1);
            if (row1 < M) *(float2*)(C + (size_t)row1 * N + col) = make_float2(v2, v3);
        }
    }
}

// ---------------- assemble x = concat([cls, emb[drug], tok]) ----------------
__global__ void assemble_kernel(
    const float* __restrict__ tok, const float* __restrict__ emb_table,
    const float* __restrict__ cls, const int* __restrict__ drug,
    float* __restrict__ X)
{
    int idx = blockIdx.x * blockDim.x + threadIdx.x;
    if (idx >= M_X * DD) return;
    int r = idx >> 8;
    int d = idx & 255;
    int b = r >> 10;
    int t = r & 1023;
    float val;
    if (t == 0)      val = cls[d];
    else if (t == 1) val = emb_table[(size_t)drug[b] * DD + d];
    else             val = tok[(size_t)(b * TEXPR + (t - 2)) * DD + d];
    X[idx] = val;
}

// ---------------- flash-style attention (fp32 SIMT) ----------------
__global__ void __launch_bounds__(256) attn_kernel(
    const float* __restrict__ Q, const float* __restrict__ K,
    const float* __restrict__ V, float* __restrict__ O)
{
    __shared__ float4 Ks[32 * 8];
    __shared__ float4 Vs[32 * 8];

    const int tid = threadIdx.x;
    const int bh = blockIdx.y;
    const int b = bh >> 3;
    const int h = bh & 7;
    const int qrow = blockIdx.x * 256 + tid;

    const float* Qp = Q + (size_t)(b * TT + qrow) * DD + h * DHD;
    float q[32];
    #pragma unroll
    for (int i = 0; i < 8; i++) {
        float4 v = *(const float4*)(Qp + i * 4);
        q[i * 4 + 0] = v.x; q[i * 4 + 1] = v.y;
        q[i * 4 + 2] = v.z; q[i * 4 + 3] = v.w;
    }

    float o[32];
    #pragma unroll
    for (int d = 0; d < 32; d++) o[d] = 0.0f;
    float m = -INFINITY;
    float l = 0.0f;

    const int krow = tid >> 3;
    const int kc   = tid & 7;
    const float scale = 0.0625f;

    for (int kt = 0; kt < TT; kt += 32) {
        const float* Kp = K + (size_t)(b * TT + kt + krow) * DD + h * DHD + kc * 4;
        const float* Vp = V + (size_t)(b * TT + kt + krow) * DD + h * DHD + kc * 4;
        Ks[krow * 8 + kc] = *(const float4*)Kp;
        Vs[krow * 8 + kc] = *(const float4*)Vp;
        __syncthreads();

        float s[32];
        float tmax = -INFINITY;
        #pragma unroll
        for (int j = 0; j < 32; j++) {
            float acc = 0.0f;
            #pragma unroll
            for (int d = 0; d < 8; d++) {
                float4 kv = Ks[j * 8 + d];
                acc += q[d * 4 + 0] * kv.x + q[d * 4 + 1] * kv.y
                     + q[d * 4 + 2] * kv.z + q[d * 4 + 3] * kv.w;
            }
            s[j] = acc * scale;
            tmax = fmaxf(tmax, s[j]);
        }
        float newm = fmaxf(m, tmax);
        float corr = __expf(m - newm);
        l *= corr;
        #pragma unroll
        for (int d = 0; d < 32; d++) o[d] *= corr;

        #pragma unroll
        for (int j = 0; j < 32; j++) {
            float p = __expf(s[j] - newm);
            l += p;
            #pragma unroll
            for (int d = 0; d < 8; d++) {
                float4 vv = Vs[j * 8 + d];
                o[d * 4 + 0] += p * vv.x; o[d * 4 + 1] += p * vv.y;
                o[d * 4 + 2] += p * vv.z; o[d * 4 + 3] += p * vv.w;
            }
        }
        m = newm;
        __syncthreads();
    }

    float inv = 1.0f / l;
    float* Op = O + (size_t)(b * TT + qrow) * DD + h * DHD;
    #pragma unroll
    for (int i = 0; i < 8; i++) {
        *(float4*)(Op + i * 4) = make_float4(o[i * 4 + 0] * inv, o[i * 4 + 1] * inv,
                                             o[i * 4 + 2] * inv, o[i * 4 + 3] * inv);
    }
}

// ---------------- fused residual-add + LayerNorm (in-place on X) ----------------
__global__ void __launch_bounds__(256) add_ln_kernel(
    float* __restrict__ X, const float* __restrict__ Tm,
    const float* __restrict__ s, const float* __restrict__ bvec)
{
    const int row = blockIdx.x;
    const int tid = threadIdx.x;
    __shared__ float red[8];
    __shared__ float meanS, rstdS;

    float v = X[(size_t)row * DD + tid] + Tm[(size_t)row * DD + tid];

    float sum = v;
    #pragma unroll
    for (int off = 16; off > 0; off >>= 1) sum += __shfl_xor_sync(0xffffffffu, sum, off);
    if ((tid & 31) == 0) red[tid >> 5] = sum;
    __syncthreads();
    if (tid < 32) {
        float t = (tid < 8) ? red[tid] : 0.0f;
        t += __shfl_xor_sync(0xffffffffu, t, 4);
        t += __shfl_xor_sync(0xffffffffu, t, 2);
        t += __shfl_xor_sync(0xffffffffu, t, 1);
        if (tid == 0) meanS = t * (1.0f / 256.0f);
    }
    __syncthreads();
    float mean = meanS;
    float dc = v - mean;

    float sq = dc * dc;
    #pragma unroll
    for (int off = 16; off > 0; off >>= 1) sq += __shfl_xor_sync(0xffffffffu, sq, off);
    __syncthreads();
    if ((tid & 31) == 0) red[tid >> 5] = sq;
    __syncthreads();
    if (tid < 32) {
        float t = (tid < 8) ? red[tid] : 0.0f;
        t += __shfl_xor_sync(0xffffffffu, t, 4);
        t += __shfl_xor_sync(0xffffffffu, t, 2);
        t += __shfl_xor_sync(0xffffffffu, t, 1);
        if (tid == 0) rstdS = rsqrtf(t * (1.0f / 256.0f) + 1e-6f);
    }
    __syncthreads();

    X[(size_t)row * DD + tid] = dc * rstdS * s[tid] + bvec[tid];
}

// ---------------- final output ----------------
__global__ void out_kernel(const float* __restrict__ X, float* __restrict__ out, int out_size)
{
    int i = blockIdx.x * blockDim.x + threadIdx.x;
    if (i >= out_size) return;
    if (i < BB * DD) {
        int b = i >> 8, d = i & 255;
        out[i] = X[(size_t)(b * TT) * DD + d];
    } else {
        out[i] = 0.0f;
    }
}

// ---------------- host launcher ----------------
extern "C" void kernel_launch(void* const* d_in, const int* in_sizes, int n_in,
                              void* d_out, int out_size)
{
    const float* x_expr    = (const float*)d_in[0];
    const int*   drug_idx  = (const int*)  d_in[1];
    // d_in[2] = attn_mask (all-True -> no-op)
    const float* tok_W1    = (const float*)d_in[3];
    const float* tok_b1    = (const float*)d_in[4];
    const float* tok_W2    = (const float*)d_in[5];
    const float* tok_b2    = (const float*)d_in[6];
    const float* emb_table = (const float*)d_in[7];
    const float* cls_token = (const float*)d_in[8];
    const float* Wq = (const float*)d_in[9];
    const float* bq = (const float*)d_in[10];
    const float* Wk = (const float*)d_in[11];
    const float* bk = (const float*)d_in[12];
    const float* Wv = (const float*)d_in[13];
    const float* bv = (const float*)d_in[14];
    const float* Wo = (const float*)d_in[15];
    const float* bo = (const float*)d_in[16];
    const float* ln1_s = (const float*)d_in[17];
    const float* ln1_b = (const float*)d_in[18];
    const float* Wf1 = (const float*)d_in[19];
    const float* bf1 = (const float*)d_in[20];
    const float* Wf2 = (const float*)d_in[21];
    const float* bf2 = (const float*)d_in[22];
    const float* ln2_s = (const float*)d_in[23];
    const float* ln2_b = (const float*)d_in[24];
    float* out = (float*)d_out;

    float *px, *ph, *ptok, *pq, *pk, *pv, *pao, *ptmp, *pffn;
    cudaGetSymbolAddress((void**)&px,   g_x);
    cudaGetSymbolAddress((void**)&ph,   g_h);
    cudaGetSymbolAddress((void**)&ptok, g_tok);
    cudaGetSymbolAddress((void**)&pq,   g_q);
    cudaGetSymbolAddress((void**)&pk,   g_k);
    cudaGetSymbolAddress((void**)&pv,   g_v);
    cudaGetSymbolAddress((void**)&pao,  g_ao);
    cudaGetSymbolAddress((void**)&ptmp, g_tmp);
    cudaGetSymbolAddress((void**)&pffn, g_ffn);

    // token MLP (tensor-core)
    {
        dim3 grid1(DD / 64, (M_TOK + 127) / 128);
        gemm_tc<1><<<grid1, 256>>>(x_expr, tok_W1, tok_b1, ph, M_TOK, DD, DIN);
        gemm_tc<1><<<grid1, 256>>>(ph, tok_W2, tok_b2, ptok, M_TOK, DD, DD);
    }
    assemble_kernel<<<(M_X * DD + 255) / 256, 256>>>(ptok, emb_table, cls_token, drug_idx, px);

    dim3 gD(DD / 64, M_X / 128);   // N=256 GEMMs
    dim3 gF(FF / 64, M_X / 128);   // N=512 GEMM
    dim3 gA(TT / 256, BB * HH);

    for (int l = 0; l < LL; l++) {
        const float* wq = Wq + (size_t)l * DD * DD;
        const float* wk = Wk + (size_t)l * DD * DD;
        const float* wv = Wv + (size_t)l * DD * DD;
        const float* wo = Wo + (size_t)l * DD * DD;
        gemm_tc<0><<<gD, 256>>>(px, wq, bq + l * DD, pq, M_X, DD, DD);
        gemm_tc<0><<<gD, 256>>>(px, wk, bk + l * DD, pk, M_X, DD, DD);
        gemm_tc<0><<<gD, 256>>>(px, wv, bv + l * DD, pv, M_X, DD, DD);
        attn_kernel<<<gA, 256>>>(pq, pk, pv, pao);
        gemm_tc<0><<<gD, 256>>>(pao, wo, bo + l * DD, ptmp, M_X, DD, DD);
        add_ln_kernel<<<M_X, 256>>>(px, ptmp, ln1_s + l * DD, ln1_b + l * DD);
        gemm_tc<1><<<gF, 256>>>(px, Wf1 + (size_t)l * DD * FF, bf1 + l * FF, pffn, M_X, FF, DD);
        gemm_tc<0><<<gD, 256>>>(pffn, Wf2 + (size_t)l * FF * DD, bf2 + l * DD, ptmp, M_X, DD, FF);
        add_ln_kernel<<<M_X, 256>>>(px, ptmp, ln2_s + l * DD, ln2_b + l * DD);
    }

    out_kernel<<<(out_size + 255) / 256, 256>>>(px, out, out_size);
}

// round 4
// speedup vs baseline: 2.6470x; 1.7897x over previous
#include <cuda_runtime.h>
#include <math.h>

#define BB 4
#define TT 1024
#define TEXPR 1022
#define DIN 64
#define DD 256
#define HH 8
#define DHD 32
#define LL 4
#define FF 512
#define M_TOK (BB*TEXPR)   // 4088
#define M_X (BB*TT)        // 4096
#define LOG2E 1.4426950408889634f

// ---------------- scratch ----------------
__device__ float g_h  [M_TOK*DD];
__device__ float g_tok[M_TOK*DD];
__device__ float g_x  [M_X*DD];
__device__ float g_q  [M_X*DD];
__device__ float g_k  [M_X*DD];
__device__ float g_v  [M_X*DD];
__device__ float g_ao [M_X*DD];
__device__ float g_tmp[M_X*DD];
__device__ float g_ffn[M_X*FF];

// ---------------- helpers ----------------
__device__ __forceinline__ float gelu_tanh(float x) {
    float x3 = x * x * x;
    return 0.5f * x * (1.0f + tanhf(0.7978845608028654f * (x + 0.044715f * x3)));
}

__device__ __forceinline__ unsigned f2tf(float x) {
    unsigned r;
    asm("cvt.rna.tf32.f32 %0, %1;" : "=r"(r) : "f"(x));
    return r;
}

__device__ __forceinline__ void mma_tf32(float c[4], const unsigned a[4], const unsigned b[2]) {
    asm volatile(
        "mma.sync.aligned.m16n8k8.row.col.f32.tf32.tf32.f32 "
        "{%0,%1,%2,%3}, {%4,%5,%6,%7}, {%8,%9}, {%0,%1,%2,%3};\n"
        : "+f"(c[0]), "+f"(c[1]), "+f"(c[2]), "+f"(c[3])
        : "r"(a[0]), "r"(a[1]), "r"(a[2]), "r"(a[3]), "r"(b[0]), "r"(b[1]));
}

// ---------------- tf32 tensor-core GEMM body ----------------
// 128x64 block tile, BK=32, 256 threads (8 warps 4x2), warp tile 32x32.
template<int ACT>
__device__ __forceinline__ void gemm_body(
    const float* __restrict__ A, const float* __restrict__ W,
    const float* __restrict__ bias, float* __restrict__ C,
    int M, int N, int K)
{
    __shared__ unsigned As[128][36];
    __shared__ unsigned Bs[32][72];

    const int tid  = threadIdx.x;
    const int lane = tid & 31;
    const int warp = tid >> 5;
    const int wm   = warp >> 1;
    const int wn   = warp & 1;
    const int bm   = blockIdx.y * 128;
    const int bn   = blockIdx.x * 64;
    const int g    = lane >> 2;
    const int tg   = lane & 3;

    float acc[2][4][4];
    #pragma unroll
    for (int i = 0; i < 2; i++)
        #pragma unroll
        for (int j = 0; j < 4; j++)
            #pragma unroll
            for (int r = 0; r < 4; r++) acc[i][j][r] = 0.0f;

    int arow[4], acol[4], brow[2], bcol[2];
    #pragma unroll
    for (int i = 0; i < 4; i++) { int idx = tid + i * 256; arow[i] = idx >> 3; acol[i] = (idx & 7) * 4; }
    #pragma unroll
    for (int i = 0; i < 2; i++) { int idx = tid + i * 256; brow[i] = idx >> 4; bcol[i] = (idx & 15) * 4; }

    float4 ra[4], rb[2];
    auto ldtile = [&](int kt) {
        #pragma unroll
        for (int i = 0; i < 4; i++) {
            if (bm + arow[i] < M)
                ra[i] = *(const float4*)(A + (size_t)(bm + arow[i]) * K + kt + acol[i]);
            else
                ra[i] = make_float4(0.f, 0.f, 0.f, 0.f);
        }
        #pragma unroll
        for (int i = 0; i < 2; i++)
            rb[i] = *(const float4*)(W + (size_t)(kt + brow[i]) * N + bn + bcol[i]);
    };

    ldtile(0);

    for (int kt = 0; kt < K; kt += 32) {
        __syncthreads();
        #pragma unroll
        for (int i = 0; i < 4; i++)
            *(uint4*)&As[arow[i]][acol[i]] =
                make_uint4(f2tf(ra[i].x), f2tf(ra[i].y), f2tf(ra[i].z), f2tf(ra[i].w));
        #pragma unroll
        for (int i = 0; i < 2; i++)
            *(uint4*)&Bs[brow[i]][bcol[i]] =
                make_uint4(f2tf(rb[i].x), f2tf(rb[i].y), f2tf(rb[i].z), f2tf(rb[i].w));
        __syncthreads();

        if (kt + 32 < K) ldtile(kt + 32);

        #pragma unroll
        for (int ks = 0; ks < 4; ks++) {
            const int k = ks * 8;
            unsigned a[2][4], b[4][2];
            #pragma unroll
            for (int i = 0; i < 2; i++) {
                const int r = wm * 32 + i * 16;
                a[i][0] = As[r + g][k + tg];
                a[i][1] = As[r + g + 8][k + tg];
                a[i][2] = As[r + g][k + tg + 4];
                a[i][3] = As[r + g + 8][k + tg + 4];
            }
            #pragma unroll
            for (int j = 0; j < 4; j++) {
                const int c = wn * 32 + j * 8 + g;
                b[j][0] = Bs[k + tg][c];
                b[j][1] = Bs[k + tg + 4][c];
            }
            #pragma unroll
            for (int i = 0; i < 2; i++)
                #pragma unroll
                for (int j = 0; j < 4; j++)
                    mma_tf32(acc[i][j], a[i], b[j]);
        }
    }

    #pragma unroll
    for (int i = 0; i < 2; i++) {
        #pragma unroll
        for (int j = 0; j < 4; j++) {
            const int col = bn + wn * 32 + j * 8 + tg * 2;
            const float b0 = bias[col], b1 = bias[col + 1];
            const int row0 = bm + wm * 32 + i * 16 + g;
            const int row1 = row0 + 8;
            float v0 = acc[i][j][0] + b0, v1 = acc[i][j][1] + b1;
            float v2 = acc[i][j][2] + b0, v3 = acc[i][j][3] + b1;
            if (ACT == 1) { v0 = gelu_tanh(v0); v1 = gelu_tanh(v1); v2 = gelu_tanh(v2); v3 = gelu_tanh(v3); }
            if (row0 < M) *(float2*)(C + (size_t)row0 * N + col) = make_float2(v0, v1);
            if (row1 < M) *(float2*)(C + (size_t)row1 * N + col) = make_float2(v2, v3);
        }
    }
}

template<int ACT>
__global__ void __launch_bounds__(256) gemm_tc(
    const float* __restrict__ A, const float* __restrict__ W,
    const float* __restrict__ bias, float* __restrict__ C,
    int M, int N, int K)
{
    gemm_body<ACT>(A, W, bias, C, M, N, K);
}

// QKV: 3 GEMMs in one launch via blockIdx.z
__global__ void __launch_bounds__(256) gemm_qkv(
    const float* __restrict__ X,
    const float* __restrict__ Wq, const float* __restrict__ Wk, const float* __restrict__ Wv,
    const float* __restrict__ bq, const float* __restrict__ bk, const float* __restrict__ bv,
    float* __restrict__ Oq, float* __restrict__ Ok, float* __restrict__ Ov)
{
    const float* W; const float* bias; float* C;
    if (blockIdx.z == 0)      { W = Wq; bias = bq; C = Oq; }
    else if (blockIdx.z == 1) { W = Wk; bias = bk; C = Ok; }
    else                      { W = Wv; bias = bv; C = Ov; }
    gemm_body<0>(X, W, bias, C, M_X, DD, DD);
}

// ---------------- assemble ----------------
__global__ void assemble_kernel(
    const float* __restrict__ tok, const float* __restrict__ emb_table,
    const float* __restrict__ cls, const int* __restrict__ drug,
    float* __restrict__ X)
{
    int idx = blockIdx.x * blockDim.x + threadIdx.x;
    if (idx >= M_X * DD) return;
    int r = idx >> 8;
    int d = idx & 255;
    int b = r >> 10;
    int t = r & 1023;
    float val;
    if (t == 0)      val = cls[d];
    else if (t == 1) val = emb_table[(size_t)drug[b] * DD + d];
    else             val = tok[(size_t)(b * TEXPR + (t - 2)) * DD + d];
    X[idx] = val;
}

// ---------------- tensor-core flash attention ----------------
// Block: 256 threads = 8 warps. Q-tile 128 rows (16/warp). KV tiles of 128 rows.
// grid (TT/128, B*H).
__global__ void __launch_bounds__(256) attn_tc(
    const float* __restrict__ Q, const float* __restrict__ K,
    const float* __restrict__ V, float* __restrict__ O)
{
    __shared__ unsigned Ks[128][36];   // [kvrow][dh], stride 36 -> conflict-free
    __shared__ unsigned Vs[128][40];   // [kvrow][dh], stride 40 -> conflict-free

    const int tid  = threadIdx.x;
    const int lane = tid & 31;
    const int warp = tid >> 5;
    const int g    = lane >> 2;
    const int tg   = lane & 3;
    const int bh = blockIdx.y;
    const int b = bh >> 3, h = bh & 7;
    const int q0 = blockIdx.x * 128;
    const size_t base = (size_t)(b * TT) * DD + h * DHD;

    const float qscale = 0.0625f * LOG2E;  // 1/sqrt(256) * log2(e)

    const int rowA = q0 + warp * 16 + g;
    const int rowB = rowA + 8;

    // Q fragments (A operand, m16k8 x 4 k-steps), scale folded in
    unsigned aq[4][4];
    #pragma unroll
    for (int ks = 0; ks < 4; ks++) {
        aq[ks][0] = f2tf(Q[base + (size_t)rowA * DD + ks * 8 + tg] * qscale);
        aq[ks][1] = f2tf(Q[base + (size_t)rowB * DD + ks * 8 + tg] * qscale);
        aq[ks][2] = f2tf(Q[base + (size_t)rowA * DD + ks * 8 + tg + 4] * qscale);
        aq[ks][3] = f2tf(Q[base + (size_t)rowB * DD + ks * 8 + tg + 4] * qscale);
    }

    float o[4][4];
    #pragma unroll
    for (int n = 0; n < 4; n++)
        #pragma unroll
        for (int r = 0; r < 4; r++) o[n][r] = 0.0f;
    float m0 = -INFINITY, m1 = -INFINITY, l0 = 0.0f, l1 = 0.0f;

    const int src_lo = (lane & ~3) | (tg >> 1);
    const int src_hi = src_lo | 2;
    const bool odd = tg & 1;

    for (int kt = 0; kt < TT; kt += 128) {
        // stage K,V tile as tf32
        #pragma unroll
        for (int i = 0; i < 4; i++) {
            int idx = tid + i * 256;
            int r = idx >> 3, c = (idx & 7) * 4;
            const float4 kv = *(const float4*)(K + base + (size_t)(kt + r) * DD + c);
            *(uint4*)&Ks[r][c] = make_uint4(f2tf(kv.x), f2tf(kv.y), f2tf(kv.z), f2tf(kv.w));
            const float4 vv = *(const float4*)(V + base + (size_t)(kt + r) * DD + c);
            *(uint4*)&Vs[r][c] = make_uint4(f2tf(vv.x), f2tf(vv.y), f2tf(vv.z), f2tf(vv.w));
        }
        __syncthreads();

        // S = Q K^T (in log2 units)
        float s[16][4];
        #pragma unroll
        for (int j = 0; j < 16; j++) {
            s[j][0] = s[j][1] = s[j][2] = s[j][3] = 0.0f;
            #pragma unroll
            for (int ks = 0; ks < 4; ks++) {
                unsigned bf[2];
                bf[0] = Ks[j * 8 + g][ks * 8 + tg];
                bf[1] = Ks[j * 8 + g][ks * 8 + tg + 4];
                mma_tf32(s[j], aq[ks], bf);
            }
        }

        // online softmax
        float tmax0 = -INFINITY, tmax1 = -INFINITY;
        #pragma unroll
        for (int j = 0; j < 16; j++) {
            tmax0 = fmaxf(tmax0, fmaxf(s[j][0], s[j][1]));
            tmax1 = fmaxf(tmax1, fmaxf(s[j][2], s[j][3]));
        }
        tmax0 = fmaxf(tmax0, __shfl_xor_sync(0xffffffffu, tmax0, 1));
        tmax0 = fmaxf(tmax0, __shfl_xor_sync(0xffffffffu, tmax0, 2));
        tmax1 = fmaxf(tmax1, __shfl_xor_sync(0xffffffffu, tmax1, 1));
        tmax1 = fmaxf(tmax1, __shfl_xor_sync(0xffffffffu, tmax1, 2));
        float nm0 = fmaxf(m0, tmax0), nm1 = fmaxf(m1, tmax1);
        float c0 = exp2f(m0 - nm0), c1 = exp2f(m1 - nm1);
        l0 *= c0; l1 *= c1;
        #pragma unroll
        for (int n = 0; n < 4; n++) {
            o[n][0] *= c0; o[n][1] *= c0;
            o[n][2] *= c1; o[n][3] *= c1;
        }
        #pragma unroll
        for (int j = 0; j < 16; j++) {
            s[j][0] = exp2f(s[j][0] - nm0);
            s[j][1] = exp2f(s[j][1] - nm0);
            s[j][2] = exp2f(s[j][2] - nm1);
            s[j][3] = exp2f(s[j][3] - nm1);
            l0 += s[j][0] + s[j][1];
            l1 += s[j][2] + s[j][3];
        }
        m0 = nm0; m1 = nm1;

        // O += P V : exchange C-frag -> A-frag via quad shuffles
        #pragma unroll
        for (int j = 0; j < 16; j++) {
            float v0 = __shfl_sync(0xffffffffu, s[j][0], src_lo);
            float v1 = __shfl_sync(0xffffffffu, s[j][1], src_lo);
            float v2 = __shfl_sync(0xffffffffu, s[j][2], src_lo);
            float v3 = __shfl_sync(0xffffffffu, s[j][3], src_lo);
            float w0 = __shfl_sync(0xffffffffu, s[j][0], src_hi);
            float w1 = __shfl_sync(0xffffffffu, s[j][1], src_hi);
            float w2 = __shfl_sync(0xffffffffu, s[j][2], src_hi);
            float w3 = __shfl_sync(0xffffffffu, s[j][3], src_hi);
            unsigned a[4];
            a[0] = f2tf(odd ? v1 : v0);   // (row g,   k tg)
            a[1] = f2tf(odd ? v3 : v2);   // (row g+8, k tg)
            a[2] = f2tf(odd ? w1 : w0);   // (row g,   k tg+4)
            a[3] = f2tf(odd ? w3 : w2);   // (row g+8, k tg+4)
            #pragma unroll
            for (int n = 0; n < 4; n++) {
                unsigned bf[2];
                bf[0] = Vs[j * 8 + tg][n * 8 + g];
                bf[1] = Vs[j * 8 + tg + 4][n * 8 + g];
                mma_tf32(o[n], a, bf);
            }
        }
        __syncthreads();
    }

    l0 += __shfl_xor_sync(0xffffffffu, l0, 1);
    l0 += __shfl_xor_sync(0xffffffffu, l0, 2);
    l1 += __shfl_xor_sync(0xffffffffu, l1, 1);
    l1 += __shfl_xor_sync(0xffffffffu, l1, 2);
    float inv0 = 1.0f / l0, inv1 = 1.0f / l1;

    #pragma unroll
    for (int n = 0; n < 4; n++) {
        *(float2*)(O + base + (size_t)rowA * DD + n * 8 + 2 * tg) =
            make_float2(o[n][0] * inv0, o[n][1] * inv0);
        *(float2*)(O + base + (size_t)rowB * DD + n * 8 + 2 * tg) =
            make_float2(o[n][2] * inv1, o[n][3] * inv1);
    }
}

// ---------------- fused residual-add + LayerNorm ----------------
__global__ void __launch_bounds__(256) add_ln_kernel(
    float* __restrict__ X, const float* __restrict__ Tm,
    const float* __restrict__ s, const float* __restrict__ bvec)
{
    const int row = blockIdx.x;
    const int tid = threadIdx.x;
    __shared__ float red[8];
    __shared__ float meanS, rstdS;

    float v = X[(size_t)row * DD + tid] + Tm[(size_t)row * DD + tid];

    float sum = v;
    #pragma unroll
    for (int off = 16; off > 0; off >>= 1) sum += __shfl_xor_sync(0xffffffffu, sum, off);
    if ((tid & 31) == 0) red[tid >> 5] = sum;
    __syncthreads();
    if (tid < 32) {
        float t = (tid < 8) ? red[tid] : 0.0f;
        t += __shfl_xor_sync(0xffffffffu, t, 4);
        t += __shfl_xor_sync(0xffffffffu, t, 2);
        t += __shfl_xor_sync(0xffffffffu, t, 1);
        if (tid == 0) meanS = t * (1.0f / 256.0f);
    }
    __syncthreads();
    float mean = meanS;
    float dc = v - mean;

    float sq = dc * dc;
    #pragma unroll
    for (int off = 16; off > 0; off >>= 1) sq += __shfl_xor_sync(0xffffffffu, sq, off);
    __syncthreads();
    if ((tid & 31) == 0) red[tid >> 5] = sq;
    __syncthreads();
    if (tid < 32) {
        float t = (tid < 8) ? red[tid] : 0.0f;
        t += __shfl_xor_sync(0xffffffffu, t, 4);
        t += __shfl_xor_sync(0xffffffffu, t, 2);
        t += __shfl_xor_sync(0xffffffffu, t, 1);
        if (tid == 0) rstdS = rsqrtf(t * (1.0f / 256.0f) + 1e-6f);
    }
    __syncthreads();

    X[(size_t)row * DD + tid] = dc * rstdS * s[tid] + bvec[tid];
}

// ---------------- final output ----------------
__global__ void out_kernel(const float* __restrict__ X, float* __restrict__ out, int out_size)
{
    int i = blockIdx.x * blockDim.x + threadIdx.x;
    if (i >= out_size) return;
    if (i < BB * DD) {
        int b = i >> 8, d = i & 255;
        out[i] = X[(size_t)(b * TT) * DD + d];
    } else {
        out[i] = 0.0f;
    }
}

// ---------------- host launcher ----------------
extern "C" void kernel_launch(void* const* d_in, const int* in_sizes, int n_in,
                              void* d_out, int out_size)
{
    const float* x_expr    = (const float*)d_in[0];
    const int*   drug_idx  = (const int*)  d_in[1];
    // d_in[2] = attn_mask (all-True -> no-op)
    const float* tok_W1    = (const float*)d_in[3];
    const float* tok_b1    = (const float*)d_in[4];
    const float* tok_W2    = (const float*)d_in[5];
    const float* tok_b2    = (const float*)d_in[6];
    const float* emb_table = (const float*)d_in[7];
    const float* cls_token = (const float*)d_in[8];
    const float* Wq = (const float*)d_in[9];
    const float* bq = (const float*)d_in[10];
    const float* Wk = (const float*)d_in[11];
    const float* bk = (const float*)d_in[12];
    const float* Wv = (const float*)d_in[13];
    const float* bv = (const float*)d_in[14];
    const float* Wo = (const float*)d_in[15];
    const float* bo = (const float*)d_in[16];
    const float* ln1_s = (const float*)d_in[17];
    const float* ln1_b = (const float*)d_in[18];
    const float* Wf1 = (const float*)d_in[19];
    const float* bf1 = (const float*)d_in[20];
    const float* Wf2 = (const float*)d_in[21];
    const float* bf2 = (const float*)d_in[22];
    const float* ln2_s = (const float*)d_in[23];
    const float* ln2_b = (const float*)d_in[24];
    float* out = (float*)d_out;

    float *px, *ph, *ptok, *pq, *pk, *pv, *pao, *ptmp, *pffn;
    cudaGetSymbolAddress((void**)&px,   g_x);
    cudaGetSymbolAddress((void**)&ph,   g_h);
    cudaGetSymbolAddress((void**)&ptok, g_tok);
    cudaGetSymbolAddress((void**)&pq,   g_q);
    cudaGetSymbolAddress((void**)&pk,   g_k);
    cudaGetSymbolAddress((void**)&pv,   g_v);
    cudaGetSymbolAddress((void**)&pao,  g_ao);
    cudaGetSymbolAddress((void**)&ptmp, g_tmp);
    cudaGetSymbolAddress((void**)&pffn, g_ffn);

    {
        dim3 grid1(DD / 64, (M_TOK + 127) / 128);
        gemm_tc<1><<<grid1, 256>>>(x_expr, tok_W1, tok_b1, ph, M_TOK, DD, DIN);
        gemm_tc<1><<<grid1, 256>>>(ph, tok_W2, tok_b2, ptok, M_TOK, DD, DD);
    }
    assemble_kernel<<<(M_X * DD + 255) / 256, 256>>>(ptok, emb_table, cls_token, drug_idx, px);

    dim3 gD(DD / 64, M_X / 128);         // N=256 GEMMs
    dim3 gQKV(DD / 64, M_X / 128, 3);    // fused QKV
    dim3 gF(FF / 64, M_X / 128);         // N=512 GEMM
    dim3 gA(TT / 128, BB * HH);          // attention

    for (int l = 0; l < LL; l++) {
        gemm_qkv<<<gQKV, 256>>>(px,
            Wq + (size_t)l * DD * DD, Wk + (size_t)l * DD * DD, Wv + (size_t)l * DD * DD,
            bq + l * DD, bk + l * DD, bv + l * DD,
            pq, pk, pv);
        attn_tc<<<gA, 256>>>(pq, pk, pv, pao);
        gemm_tc<0><<<gD, 256>>>(pao, Wo + (size_t)l * DD * DD, bo + l * DD, ptmp, M_X, DD, DD);
        add_ln_kernel<<<M_X, 256>>>(px, ptmp, ln1_s + l * DD, ln1_b + l * DD);
        gemm_tc<1><<<gF, 256>>>(px, Wf1 + (size_t)l * DD * FF, bf1 + l * FF, pffn, M_X, FF, DD);
        gemm_tc<0><<<gD, 256>>>(pffn, Wf2 + (size_t)l * FF * DD, bf2 + l * DD, ptmp, M_X, DD, FF);
        add_ln_kernel<<<M_X, 256>>>(px, ptmp, ln2_s + l * DD, ln2_b + l * DD);
    }

    out_kernel<<<(out_size + 255) / 256, 256>>>(px, out, out_size);
}

// round 5
// speedup vs baseline: 2.6493x; 1.0009x over previous
#include <cuda_runtime.h>
#include <math.h>

#define BB 4
#define TT 1024
#define TEXPR 1022
#define DIN 64
#define DD 256
#define HH 8
#define DHD 32
#define LL 4
#define FF 512
#define M_TOK (BB*TEXPR)   // 4088
#define M_X (BB*TT)        // 4096
#define LOG2E 1.4426950408889634f

// ---------------- scratch ----------------
__device__ float g_h  [M_TOK*DD];
__device__ float g_tok[M_TOK*DD];
__device__ float g_x  [M_X*DD];
__device__ float g_q  [M_X*DD];
__device__ float g_k  [M_X*DD];
__device__ float g_v  [M_X*DD];
__device__ float g_ao [M_X*DD];
__device__ float g_tmp[M_X*DD];
__device__ float g_ffn[M_X*FF];

// ---------------- helpers ----------------
__device__ __forceinline__ float gelu_tanh(float x) {
    float x3 = x * x * x;
    return 0.5f * x * (1.0f + tanhf(0.7978845608028654f * (x + 0.044715f * x3)));
}

__device__ __forceinline__ unsigned f2tf(float x) {
    unsigned r;
    asm("cvt.rna.tf32.f32 %0, %1;" : "=r"(r) : "f"(x));
    return r;
}

__device__ __forceinline__ void mma_tf32(float c[4], const unsigned a[4], const unsigned b[2]) {
    asm volatile(
        "mma.sync.aligned.m16n8k8.row.col.f32.tf32.tf32.f32 "
        "{%0,%1,%2,%3}, {%4,%5,%6,%7}, {%8,%9}, {%0,%1,%2,%3};\n"
        : "+f"(c[0]), "+f"(c[1]), "+f"(c[2]), "+f"(c[3])
        : "r"(a[0]), "r"(a[1]), "r"(a[2]), "r"(a[3]), "r"(b[0]), "r"(b[1]));
}

// ---------------- tf32 tensor-core GEMM body ----------------
// 128x64 block tile, BK=32, 256 threads (8 warps 4x2), warp tile 32x32.
template<int ACT>
__device__ __forceinline__ void gemm_body(
    const float* __restrict__ A, const float* __restrict__ W,
    const float* __restrict__ bias, float* __restrict__ C,
    int M, int N, int K)
{
    __shared__ unsigned As[128][36];
    __shared__ unsigned Bs[32][72];

    const int tid  = threadIdx.x;
    const int lane = tid & 31;
    const int warp = tid >> 5;
    const int wm   = warp >> 1;
    const int wn   = warp & 1;
    const int bm   = blockIdx.y * 128;
    const int bn   = blockIdx.x * 64;
    const int g    = lane >> 2;
    const int tg   = lane & 3;

    float acc[2][4][4];
    #pragma unroll
    for (int i = 0; i < 2; i++)
        #pragma unroll
        for (int j = 0; j < 4; j++)
            #pragma unroll
            for (int r = 0; r < 4; r++) acc[i][j][r] = 0.0f;

    int arow[4], acol[4], brow[2], bcol[2];
    #pragma unroll
    for (int i = 0; i < 4; i++) { int idx = tid + i * 256; arow[i] = idx >> 3; acol[i] = (idx & 7) * 4; }
    #pragma unroll
    for (int i = 0; i < 2; i++) { int idx = tid + i * 256; brow[i] = idx >> 4; bcol[i] = (idx & 15) * 4; }

    float4 ra[4], rb[2];
    auto ldtile = [&](int kt) {
        #pragma unroll
        for (int i = 0; i < 4; i++) {
            if (bm + arow[i] < M)
                ra[i] = *(const float4*)(A + (size_t)(bm + arow[i]) * K + kt + acol[i]);
            else
                ra[i] = make_float4(0.f, 0.f, 0.f, 0.f);
        }
        #pragma unroll
        for (int i = 0; i < 2; i++)
            rb[i] = *(const float4*)(W + (size_t)(kt + brow[i]) * N + bn + bcol[i]);
    };

    ldtile(0);

    for (int kt = 0; kt < K; kt += 32) {
        __syncthreads();
        #pragma unroll
        for (int i = 0; i < 4; i++)
            *(uint4*)&As[arow[i]][acol[i]] =
                make_uint4(f2tf(ra[i].x), f2tf(ra[i].y), f2tf(ra[i].z), f2tf(ra[i].w));
        #pragma unroll
        for (int i = 0; i < 2; i++)
            *(uint4*)&Bs[brow[i]][bcol[i]] =
                make_uint4(f2tf(rb[i].x), f2tf(rb[i].y), f2tf(rb[i].z), f2tf(rb[i].w));
        __syncthreads();

        if (kt + 32 < K) ldtile(kt + 32);

        #pragma unroll
        for (int ks = 0; ks < 4; ks++) {
            const int k = ks * 8;
            unsigned a[2][4], b[4][2];
            #pragma unroll
            for (int i = 0; i < 2; i++) {
                const int r = wm * 32 + i * 16;
                a[i][0] = As[r + g][k + tg];
                a[i][1] = As[r + g + 8][k + tg];
                a[i][2] = As[r + g][k + tg + 4];
                a[i][3] = As[r + g + 8][k + tg + 4];
            }
            #pragma unroll
            for (int j = 0; j < 4; j++) {
                const int c = wn * 32 + j * 8 + g;
                b[j][0] = Bs[k + tg][c];
                b[j][1] = Bs[k + tg + 4][c];
            }
            #pragma unroll
            for (int i = 0; i < 2; i++)
                #pragma unroll
                for (int j = 0; j < 4; j++)
                    mma_tf32(acc[i][j], a[i], b[j]);
        }
    }

    #pragma unroll
    for (int i = 0; i < 2; i++) {
        #pragma unroll
        for (int j = 0; j < 4; j++) {
            const int col = bn + wn * 32 + j * 8 + tg * 2;
            const float b0 = bias[col], b1 = bias[col + 1];
            const int row0 = bm + wm * 32 + i * 16 + g;
            const int row1 = row0 + 8;
            float v0 = acc[i][j][0] + b0, v1 = acc[i][j][1] + b1;
            float v2 = acc[i][j][2] + b0, v3 = acc[i][j][3] + b1;
            if (ACT == 1) { v0 = gelu_tanh(v0); v1 = gelu_tanh(v1); v2 = gelu_tanh(v2); v3 = gelu_tanh(v3); }
            if (row0 < M) *(float2*)(C + (size_t)row0 * N + col) = make_float2(v0, v1);
            if (row1 < M) *(float2*)(C + (size_t)row1 * N + col) = make_float2(v2, v3);
        }
    }
}

template<int ACT>
__global__ void __launch_bounds__(256) gemm_tc(
    const float* __restrict__ A, const float* __restrict__ W,
    const float* __restrict__ bias, float* __restrict__ C,
    int M, int N, int K)
{
    gemm_body<ACT>(A, W, bias, C, M, N, K);
}

// QKV: 3 GEMMs in one launch via blockIdx.z
__global__ void __launch_bounds__(256) gemm_qkv(
    const float* __restrict__ X,
    const float* __restrict__ Wq, const float* __restrict__ Wk, const float* __restrict__ Wv,
    const float* __restrict__ bq, const float* __restrict__ bk, const float* __restrict__ bv,
    float* __restrict__ Oq, float* __restrict__ Ok, float* __restrict__ Ov)
{
    const float* W; const float* bias; float* C;
    if (blockIdx.z == 0)      { W = Wq; bias = bq; C = Oq; }
    else if (blockIdx.z == 1) { W = Wk; bias = bk; C = Ok; }
    else                      { W = Wv; bias = bv; C = Ov; }
    gemm_body<0>(X, W, bias, C, M_X, DD, DD);
}

// ---------------- assemble ----------------
__global__ void assemble_kernel(
    const float* __restrict__ tok, const float* __restrict__ emb_table,
    const float* __restrict__ cls, const int* __restrict__ drug,
    float* __restrict__ X)
{
    int idx = blockIdx.x * blockDim.x + threadIdx.x;
    if (idx >= M_X * DD) return;
    int r = idx >> 8;
    int d = idx & 255;
    int b = r >> 10;
    int t = r & 1023;
    float val;
    if (t == 0)      val = cls[d];
    else if (t == 1) val = emb_table[(size_t)drug[b] * DD + d];
    else             val = tok[(size_t)(b * TEXPR + (t - 2)) * DD + d];
    X[idx] = val;
}

// ---------------- tensor-core flash attention ----------------
// Block: 256 threads = 8 warps. Q-tile 128 rows (16/warp). KV tiles of 128 rows.
// grid (TT/128, B*H).
__global__ void __launch_bounds__(256) attn_tc(
    const float* __restrict__ Q, const float* __restrict__ K,
    const float* __restrict__ V, float* __restrict__ O)
{
    __shared__ unsigned Ks[128][36];   // [kvrow][dh], stride 36 -> conflict-free
    __shared__ unsigned Vs[128][40];   // [kvrow][dh], stride 40 -> conflict-free

    const int tid  = threadIdx.x;
    const int lane = tid & 31;
    const int warp = tid >> 5;
    const int g    = lane >> 2;
    const int tg   = lane & 3;
    const int bh = blockIdx.y;
    const int b = bh >> 3, h = bh & 7;
    const int q0 = blockIdx.x * 128;
    const size_t base = (size_t)(b * TT) * DD + h * DHD;

    const float qscale = 0.0625f * LOG2E;  // 1/sqrt(256) * log2(e)

    const int rowA = q0 + warp * 16 + g;
    const int rowB = rowA + 8;

    // Q fragments (A operand, m16k8 x 4 k-steps), scale folded in
    unsigned aq[4][4];
    #pragma unroll
    for (int ks = 0; ks < 4; ks++) {
        aq[ks][0] = f2tf(Q[base + (size_t)rowA * DD + ks * 8 + tg] * qscale);
        aq[ks][1] = f2tf(Q[base + (size_t)rowB * DD + ks * 8 + tg] * qscale);
        aq[ks][2] = f2tf(Q[base + (size_t)rowA * DD + ks * 8 + tg + 4] * qscale);
        aq[ks][3] = f2tf(Q[base + (size_t)rowB * DD + ks * 8 + tg + 4] * qscale);
    }

    float o[4][4];
    #pragma unroll
    for (int n = 0; n < 4; n++)
        #pragma unroll
        for (int r = 0; r < 4; r++) o[n][r] = 0.0f;
    float m0 = -INFINITY, m1 = -INFINITY, l0 = 0.0f, l1 = 0.0f;

    const int src_lo = (lane & ~3) | (tg >> 1);
    const int src_hi = src_lo | 2;
    const bool odd = tg & 1;

    for (int kt = 0; kt < TT; kt += 128) {
        // stage K,V tile as tf32
        #pragma unroll
        for (int i = 0; i < 4; i++) {
            int idx = tid + i * 256;
            int r = idx >> 3, c = (idx & 7) * 4;
            const float4 kv = *(const float4*)(K + base + (size_t)(kt + r) * DD + c);
            *(uint4*)&Ks[r][c] = make_uint4(f2tf(kv.x), f2tf(kv.y), f2tf(kv.z), f2tf(kv.w));
            const float4 vv = *(const float4*)(V + base + (size_t)(kt + r) * DD + c);
            *(uint4*)&Vs[r][c] = make_uint4(f2tf(vv.x), f2tf(vv.y), f2tf(vv.z), f2tf(vv.w));
        }
        __syncthreads();

        // S = Q K^T (in log2 units)
        float s[16][4];
        #pragma unroll
        for (int j = 0; j < 16; j++) {
            s[j][0] = s[j][1] = s[j][2] = s[j][3] = 0.0f;
            #pragma unroll
            for (int ks = 0; ks < 4; ks++) {
                unsigned bf[2];
                bf[0] = Ks[j * 8 + g][ks * 8 + tg];
                bf[1] = Ks[j * 8 + g][ks * 8 + tg + 4];
                mma_tf32(s[j], aq[ks], bf);
            }
        }

        // online softmax
        float tmax0 = -INFINITY, tmax1 = -INFINITY;
        #pragma unroll
        for (int j = 0; j < 16; j++) {
            tmax0 = fmaxf(tmax0, fmaxf(s[j][0], s[j][1]));
            tmax1 = fmaxf(tmax1, fmaxf(s[j][2], s[j][3]));
        }
        tmax0 = fmaxf(tmax0, __shfl_xor_sync(0xffffffffu, tmax0, 1));
        tmax0 = fmaxf(tmax0, __shfl_xor_sync(0xffffffffu, tmax0, 2));
        tmax1 = fmaxf(tmax1, __shfl_xor_sync(0xffffffffu, tmax1, 1));
        tmax1 = fmaxf(tmax1, __shfl_xor_sync(0xffffffffu, tmax1, 2));
        float nm0 = fmaxf(m0, tmax0), nm1 = fmaxf(m1, tmax1);
        float c0 = exp2f(m0 - nm0), c1 = exp2f(m1 - nm1);
        l0 *= c0; l1 *= c1;
        #pragma unroll
        for (int n = 0; n < 4; n++) {
            o[n][0] *= c0; o[n][1] *= c0;
            o[n][2] *= c1; o[n][3] *= c1;
        }
        #pragma unroll
        for (int j = 0; j < 16; j++) {
            s[j][0] = exp2f(s[j][0] - nm0);
            s[j][1] = exp2f(s[j][1] - nm0);
            s[j][2] = exp2f(s[j][2] - nm1);
            s[j][3] = exp2f(s[j][3] - nm1);
            l0 += s[j][0] + s[j][1];
            l1 += s[j][2] + s[j][3];
        }
        m0 = nm0; m1 = nm1;

        // O += P V : exchange C-frag -> A-frag via quad shuffles
        #pragma unroll
        for (int j = 0; j < 16; j++) {
            float v0 = __shfl_sync(0xffffffffu, s[j][0], src_lo);
            float v1 = __shfl_sync(0xffffffffu, s[j][1], src_lo);
            float v2 = __shfl_sync(0xffffffffu, s[j][2], src_lo);
            float v3 = __shfl_sync(0xffffffffu, s[j][3], src_lo);
            float w0 = __shfl_sync(0xffffffffu, s[j][0], src_hi);
            float w1 = __shfl_sync(0xffffffffu, s[j][1], src_hi);
            float w2 = __shfl_sync(0xffffffffu, s[j][2], src_hi);
            float w3 = __shfl_sync(0xffffffffu, s[j][3], src_hi);
            unsigned a[4];
            a[0] = f2tf(odd ? v1 : v0);   // (row g,   k tg)
            a[1] = f2tf(odd ? v3 : v2);   // (row g+8, k tg)
            a[2] = f2tf(odd ? w1 : w0);   // (row g,   k tg+4)
            a[3] = f2tf(odd ? w3 : w2);   // (row g+8, k tg+4)
            #pragma unroll
            for (int n = 0; n < 4; n++) {
                unsigned bf[2];
                bf[0] = Vs[j * 8 + tg][n * 8 + g];
                bf[1] = Vs[j * 8 + tg + 4][n * 8 + g];
                mma_tf32(o[n], a, bf);
            }
        }
        __syncthreads();
    }

    l0 += __shfl_xor_sync(0xffffffffu, l0, 1);
    l0 += __shfl_xor_sync(0xffffffffu, l0, 2);
    l1 += __shfl_xor_sync(0xffffffffu, l1, 1);
    l1 += __shfl_xor_sync(0xffffffffu, l1, 2);
    float inv0 = 1.0f / l0, inv1 = 1.0f / l1;

    #pragma unroll
    for (int n = 0; n < 4; n++) {
        *(float2*)(O + base + (size_t)rowA * DD + n * 8 + 2 * tg) =
            make_float2(o[n][0] * inv0, o[n][1] * inv0);
        *(float2*)(O + base + (size_t)rowB * DD + n * 8 + 2 * tg) =
            make_float2(o[n][2] * inv1, o[n][3] * inv1);
    }
}

// ---------------- fused residual-add + LayerNorm ----------------
__global__ void __launch_bounds__(256) add_ln_kernel(
    float* __restrict__ X, const float* __restrict__ Tm,
    const float* __restrict__ s, const float* __restrict__ bvec)
{
    const int row = blockIdx.x;
    const int tid = threadIdx.x;
    __shared__ float red[8];
    __shared__ float meanS, rstdS;

    float v = X[(size_t)row * DD + tid] + Tm[(size_t)row * DD + tid];

    float sum = v;
    #pragma unroll
    for (int off = 16; off > 0; off >>= 1) sum += __shfl_xor_sync(0xffffffffu, sum, off);
    if ((tid & 31) == 0) red[tid >> 5] = sum;
    __syncthreads();
    if (tid < 32) {
        float t = (tid < 8) ? red[tid] : 0.0f;
        t += __shfl_xor_sync(0xffffffffu, t, 4);
        t += __shfl_xor_sync(0xffffffffu, t, 2);
        t += __shfl_xor_sync(0xffffffffu, t, 1);
        if (tid == 0) meanS = t * (1.0f / 256.0f);
    }
    __syncthreads();
    float mean = meanS;
    float dc = v - mean;

    float sq = dc * dc;
    #pragma unroll
    for (int off = 16; off > 0; off >>= 1) sq += __shfl_xor_sync(0xffffffffu, sq, off);
    __syncthreads();
    if ((tid & 31) == 0) red[tid >> 5] = sq;
    __syncthreads();
    if (tid < 32) {
        float t = (tid < 8) ? red[tid] : 0.0f;
        t += __shfl_xor_sync(0xffffffffu, t, 4);
        t += __shfl_xor_sync(0xffffffffu, t, 2);
        t += __shfl_xor_sync(0xffffffffu, t, 1);
        if (tid == 0) rstdS = rsqrtf(t * (1.0f / 256.0f) + 1e-6f);
    }
    __syncthreads();

    X[(size_t)row * DD + tid] = dc * rstdS * s[tid] + bvec[tid];
}

// ---------------- final output ----------------
__global__ void out_kernel(const float* __restrict__ X, float* __restrict__ out, int out_size)
{
    int i = blockIdx.x * blockDim.x + threadIdx.x;
    if (i >= out_size) return;
    if (i < BB * DD) {
        int b = i >> 8, d = i & 255;
        out[i] = X[(size_t)(b * TT) * DD + d];
    } else {
        out[i] = 0.0f;
    }
}

// ---------------- host launcher ----------------
extern "C" void kernel_launch(void* const* d_in, const int* in_sizes, int n_in,
                              void* d_out, int out_size)
{
    const float* x_expr    = (const float*)d_in[0];
    const int*   drug_idx  = (const int*)  d_in[1];
    // d_in[2] = attn_mask (all-True -> no-op)
    const float* tok_W1    = (const float*)d_in[3];
    const float* tok_b1    = (const float*)d_in[4];
    const float* tok_W2    = (const float*)d_in[5];
    const float* tok_b2    = (const float*)d_in[6];
    const float* emb_table = (const float*)d_in[7];
    const float* cls_token = (const float*)d_in[8];
    const float* Wq = (const float*)d_in[9];
    const float* bq = (const float*)d_in[10];
    const float* Wk = (const float*)d_in[11];
    const float* bk = (const float*)d_in[12];
    const float* Wv = (const float*)d_in[13];
    const float* bv = (const float*)d_in[14];
    const float* Wo = (const float*)d_in[15];
    const float* bo = (const float*)d_in[16];
    const float* ln1_s = (const float*)d_in[17];
    const float* ln1_b = (const float*)d_in[18];
    const float* Wf1 = (const float*)d_in[19];
    const float* bf1 = (const float*)d_in[20];
    const float* Wf2 = (const float*)d_in[21];
    const float* bf2 = (const float*)d_in[22];
    const float* ln2_s = (const float*)d_in[23];
    const float* ln2_b = (const float*)d_in[24];
    float* out = (float*)d_out;

    float *px, *ph, *ptok, *pq, *pk, *pv, *pao, *ptmp, *pffn;
    cudaGetSymbolAddress((void**)&px,   g_x);
    cudaGetSymbolAddress((void**)&ph,   g_h);
    cudaGetSymbolAddress((void**)&ptok, g_tok);
    cudaGetSymbolAddress((void**)&pq,   g_q);
    cudaGetSymbolAddress((void**)&pk,   g_k);
    cudaGetSymbolAddress((void**)&pv,   g_v);
    cudaGetSymbolAddress((void**)&pao,  g_ao);
    cudaGetSymbolAddress((void**)&ptmp, g_tmp);
    cudaGetSymbolAddress((void**)&pffn, g_ffn);

    {
        dim3 grid1(DD / 64, (M_TOK + 127) / 128);
        gemm_tc<1><<<grid1, 256>>>(x_expr, tok_W1, tok_b1, ph, M_TOK, DD, DIN);
        gemm_tc<1><<<grid1, 256>>>(ph, tok_W2, tok_b2, ptok, M_TOK, DD, DD);
    }
    assemble_kernel<<<(M_X * DD + 255) / 256, 256>>>(ptok, emb_table, cls_token, drug_idx, px);

    dim3 gD(DD / 64, M_X / 128);         // N=256 GEMMs
    dim3 gQKV(DD / 64, M_X / 128, 3);    // fused QKV
    dim3 gF(FF / 64, M_X / 128);         // N=512 GEMM
    dim3 gA(TT / 128, BB * HH);          // attention

    for (int l = 0; l < LL; l++) {
        gemm_qkv<<<gQKV, 256>>>(px,
            Wq + (size_t)l * DD * DD, Wk + (size_t)l * DD * DD, Wv + (size_t)l * DD * DD,
            bq + l * DD, bk + l * DD, bv + l * DD,
            pq, pk, pv);
        attn_tc<<<gA, 256>>>(pq, pk, pv, pao);
        gemm_tc<0><<<gD, 256>>>(pao, Wo + (size_t)l * DD * DD, bo + l * DD, ptmp, M_X, DD, DD);
        add_ln_kernel<<<M_X, 256>>>(px, ptmp, ln1_s + l * DD, ln1_b + l * DD);
        gemm_tc<1><<<gF, 256>>>(px, Wf1 + (size_t)l * DD * FF, bf1 + l * FF, pffn, M_X, FF, DD);
        gemm_tc<0><<<gD, 256>>>(pffn, Wf2 + (size_t)l * FF * DD, bf2 + l * DD, ptmp, M_X, DD, FF);
        add_ln_kernel<<<M_X, 256>>>(px, ptmp, ln2_s + l * DD, ln2_b + l * DD);
    }

    out_kernel<<<(out_size + 255) / 256, 256>>>(px, out, out_size);
}